// round 12
// baseline (speedup 1.0000x reference)
#include <cuda_runtime.h>
#include <cuda_fp16.h>
#include <cstdint>
#include <math.h>

#define BATCH 16
#define ZD 256
#define OC 256
#define IC 128
#define FANIN (IC*9)          // 1152
#define NTOT (OC*FANIN)       // 294912
#define HW 64

// ---------------- device scratch (no allocation APIs) ----------------
__device__ float g_dw[BATCH*NTOT];             // delta_w [b][n]
__device__ __half g_wh[BATCH*OC*9*IC];         // weights fp16, [b][oc][tap][cin]

// fp16 mma.sync (sm_80-era PTX — valid on plain compute_103 virtual arch)
__device__ __forceinline__ void mma16816h(float* d, const uint32_t* a,
                                          uint32_t b0, uint32_t b1) {
    asm volatile(
        "mma.sync.aligned.m16n8k16.row.col.f32.f16.f16.f32 "
        "{%0,%1,%2,%3}, {%4,%5,%6,%7}, {%8,%9}, {%0,%1,%2,%3};"
        : "+f"(d[0]), "+f"(d[1]), "+f"(d[2]), "+f"(d[3])
        : "r"(a[0]), "r"(a[1]), "r"(a[2]), "r"(a[3]), "r"(b0), "r"(b1));
}

__device__ __forceinline__ uint32_t pack_h2(float a, float b) {
    __half2 h = __floats2half2_rn(a, b);
    return *reinterpret_cast<uint32_t*>(&h);
}

// k-pair permutation inside each 32B (8-pair) group: pair lp stored at
// pos(lp) = 2(lp&3) | (lp>>2). LDS.64 at byte 8*qc then returns pairs
// (qc, qc+4) = the m16n8k16 (b0,b1).
__device__ __forceinline__ int kperm_pos(int lp) { return ((lp & 3) << 1) | (lp >> 2); }

// ---------------------------------------------------------------------------
// Kernel A: delta[b][n] = sum_k z[b][k] * head_w[n][k]  via HMMA.
// 4 tiles (8 K-halves) per CTA in one software pipeline: steady-state
// compute(h) overlaps LDG(h+2); only the first half's latency is exposed.
// Block: 256 threads = 8 warps, warp = one n8 strip per tile.
// ---------------------------------------------------------------------------
#define HROW 264     // 128 k * 2B + 8B pad
#define TILES_PER_CTA 4
#define NHALF (TILES_PER_CTA*2)

__global__ void __launch_bounds__(256) gemm_hmma(const float* __restrict__ z,
                                                 const float* __restrict__ hw)
{
    __shared__ uint4 zf[512];              // A-frags: [kk(16)][lane(32)] x 16B
    __shared__ char  hws[2][64*HROW];      // B fp16 half-tiles, k-pair permuted

    const int tid   = threadIdx.x;
    const int nbase = blockIdx.x * (TILES_PER_CTA*64);

    float4 v[8];

    // per-thread staging slots: idx = u*256 + tid -> row = idx>>5, kq = idx&31
    auto load_half = [&](int h) {
        const int t = h >> 1, hk = h & 1;
        #pragma unroll
        for (int u = 0; u < 8; u++) {
            const int idx = u*256 + tid;
            const int row = idx >> 5, kq = idx & 31;
            v[u] = *(const float4*)&hw[(size_t)(nbase + t*64 + row)*ZD + hk*128 + kq*4];
        }
    };
    auto store_half = [&](int buf) {
        #pragma unroll
        for (int u = 0; u < 8; u++) {
            const int idx = u*256 + tid;
            const int row = idx >> 5, kq = idx & 31;
            const int g   = kq >> 2;
            const int lp0 = 2*(kq & 3);
            char* rp = hws[buf] + row*HROW + g*32;
            *(uint32_t*)(rp + kperm_pos(lp0)*4)     = pack_h2(v[u].x, v[u].y);
            *(uint32_t*)(rp + kperm_pos(lp0 + 1)*4) = pack_h2(v[u].z, v[u].w);
        }
    };

    // ---- prologue: LDG(0) in flight while zf is built ----
    load_half(0);

    #pragma unroll
    for (int u = 0; u < 2; u++) {
        const int s  = tid + u*256;
        const int kk = s >> 5, l = s & 31;
        const int m  = l >> 2;
        const int kb = kk*16 + 2*(l & 3);
        float2 f0 = *(const float2*)&z[m*ZD + kb];
        float2 f1 = *(const float2*)&z[(m+8)*ZD + kb];
        float2 f2 = *(const float2*)&z[m*ZD + kb + 8];
        float2 f3 = *(const float2*)&z[(m+8)*ZD + kb + 8];
        uint4 vv;
        vv.x = pack_h2(f0.x, f0.y);
        vv.y = pack_h2(f1.x, f1.y);
        vv.z = pack_h2(f2.x, f2.y);
        vv.w = pack_h2(f3.x, f3.y);
        zf[s] = vv;
    }

    store_half(0);
    load_half(1);                 // in flight during compute(0)
    __syncthreads();              // zf + hws[0] ready

    const int wid = tid >> 5, lane = tid & 31;
    const int qr = lane >> 2, qc = lane & 3;

    float d[4] = {0.f, 0.f, 0.f, 0.f};

    #pragma unroll
    for (int h = 0; h < NHALF; h++) {
        // ---- compute half h from hws[h&1] ----
        {
            const char* bp = hws[h & 1] + (wid*8 + qr)*HROW + qc*8;
            const int kk0 = (h & 1)*8;
            #pragma unroll
            for (int kk = 0; kk < 8; kk++) {
                uint4 a = zf[(kk0 + kk)*32 + lane];
                uint2 b = *(const uint2*)(bp + kk*32);
                mma16816h(d, (const uint32_t*)&a, b.x, b.y);
            }
        }
        // ---- keep the pipe full ----
        if (h < NHALF - 1) {
            store_half((h + 1) & 1);          // regs hold h+1 (LDG completed during compute)
            if (h < NHALF - 2) load_half(h + 2);
        }
        // ---- tile epilogue every 2 halves ----
        if (h & 1) {
            const int n = nbase + (h >> 1)*64 + wid*8 + 2*qc;
            *(float2*)&g_dw[(size_t)qr*NTOT + n]       = make_float2(d[0], d[1]);
            *(float2*)&g_dw[(size_t)(qr + 8)*NTOT + n] = make_float2(d[2], d[3]);
            d[0] = d[1] = d[2] = d[3] = 0.f;
        }
        if (h < NHALF - 1) __syncthreads();   // hws[(h+1)&1] ready for next iter
    }
}

// ---------------------------------------------------------------------------
// Kernel B: standardize + build weights, emit fp16, [b][oc][tap][cin].
// Transpose via smem so global writes are coalesced 8B stores.
// ---------------------------------------------------------------------------
__global__ void __launch_bounds__(128) build_w(const float* __restrict__ base)
{
    __shared__ __half ws[FANIN];        // [tap][cin]

    const int b  = blockIdx.x >> 8;
    const int oc = blockIdx.x & 255;
    const int tid = threadIdx.x;

    const float* dwp = &g_dw[(size_t)b*NTOT + oc*FANIN];

    float v[9];
    float s = 0.f, sq = 0.f;
    #pragma unroll
    for (int t = 0; t < 9; t++) {
        v[t] = dwp[tid + t*128];
        s  += v[t];
        sq += v[t]*v[t];
    }
    #pragma unroll
    for (int off = 16; off; off >>= 1) {
        s  += __shfl_xor_sync(0xffffffffu, s,  off);
        sq += __shfl_xor_sync(0xffffffffu, sq, off);
    }
    __shared__ float ss[4], ssq[4];
    const int wid = tid >> 5;
    if ((tid & 31) == 0) { ss[wid] = s; ssq[wid] = sq; }
    __syncthreads();
    s  = ss[0] + ss[1] + ss[2] + ss[3];
    sq = ssq[0] + ssq[1] + ssq[2] + ssq[3];

    const float inv_n = 1.0f / (float)FANIN;
    float mu  = s * inv_n;
    float var = sq * inv_n - mu*mu;
    float rs  = rsqrtf(var + 1e-5f);
    const float inv_sqrt2 = 0.70710678118654752440f;
    float c1 = rs * sqrtf(2.0f / (float)FANIN) * inv_sqrt2;

    const float* bw = &base[(size_t)oc*FANIN];
    #pragma unroll
    for (int t = 0; t < 9; t++) {
        int i = tid + t*128;           // i = cin*9 + tap
        int cin = i / 9, tap = i - cin*9;
        float w = bw[i]*inv_sqrt2 + (v[t] - mu)*c1;
        ws[tap*IC + cin] = __float2half(w);
    }
    __syncthreads();

    // coalesced flush: 1152 halves = 288 x 8B
    uint2* dst = (uint2*)&g_wh[(size_t)(b*OC + oc)*9*IC];
    const uint2* src = (const uint2*)ws;
    #pragma unroll
    for (int i = tid; i < 288; i += 128) dst[i] = src[i];
}

// ---------------------------------------------------------------------------
// Kernel C: implicit-GEMM conv via mma.sync fp16 single-pass, fp32 accum.
// CTA = (4 y-rows, 128-oc tile, b). 512 threads = 16 warps, warp tile 32oc x 64n.
// At the 512 MAC/cyc/SM HMMA ceiling — do not touch.
// ---------------------------------------------------------------------------
#define XS_STRIDE 144                  // bytes per (y,x) row of 64 cin fp16 (+16B pad)
#define XS_BYTES  (6*66*XS_STRIDE)     // 57024
#define A_BUF     18432                // one A buffer: 128 oc x 144B
#define SM_XS     36864                // after 2 A buffers
#define CONV_SMEM (SM_XS + XS_BYTES)   // 93888

__global__ void __launch_bounds__(512, 1) conv_mma(const float* __restrict__ x,
                                                   float* __restrict__ out)
{
    extern __shared__ char smem[];
    const int tid  = threadIdx.x;
    const int wid  = tid >> 5;
    const int lane = tid & 31;
    const int y0   = blockIdx.x * 4;
    const int oc0  = blockIdx.y * 128;
    const int b    = blockIdx.z;

    const int mw = wid & 3;       // oc quarter (32)
    const int yl = wid >> 2;      // local y row
    const int qr = lane >> 2;     // 0..7
    const int qc = lane & 3;      // 0..3

    float acc[2][8][4];
    #pragma unroll
    for (int mf = 0; mf < 2; mf++)
        #pragma unroll
        for (int nf = 0; nf < 8; nf++)
            #pragma unroll
            for (int q = 0; q < 4; q++) acc[mf][nf][q] = 0.f;

    uint4 nv[2];   // in-flight A tile, 2 chunks per thread

    // ---- helpers ----
    auto lda = [&](int it) {
        const int ch = it / 9, tap = it - ch*9;
        const size_t abase = ((size_t)((b*OC + oc0)*9 + tap))*IC + (size_t)ch*64;
        #pragma unroll
        for (int u = 0; u < 2; u++) {
            const int i = tid + u*512;
            const int row = i >> 3, j = i & 7;
            const size_t off8 = (abase + (size_t)row*(9*IC)) / 8 + j;   // uint4 idx
            nv[u] = ((const uint4*)g_wh)[off8];
        }
    };
    auto sta = [&](int buf) {
        char* base = smem + buf*A_BUF;
        #pragma unroll
        for (int u = 0; u < 2; u++) {
            const int i = tid + u*512;
            const int row = i >> 3, j = i & 7;
            *(uint4*)(base + row*XS_STRIDE + j*16) = nv[u];
        }
    };
    auto stage_x = [&](int ch) {
        for (int i = tid; i < 6*32*16; i += 512) {
            const int ys  = i >> 9;
            const int rem = i & 511;
            const int cp  = rem >> 4;      // c-pair 0..31
            const int x4  = rem & 15;
            const int gy  = y0 - 1 + ys;
            if (gy >= 0 && gy < HW) {
                const float4 v0 = *(const float4*)
                    &x[(((size_t)(b*IC + ch*64 + cp*2    ))*HW + gy)*HW + x4*4];
                const float4 v1 = *(const float4*)
                    &x[(((size_t)(b*IC + ch*64 + cp*2 + 1))*HW + gy)*HW + x4*4];
                const float f0[4] = {v0.x, v0.y, v0.z, v0.w};
                const float f1[4] = {v1.x, v1.y, v1.z, v1.w};
                #pragma unroll
                for (int q = 0; q < 4; q++) {
                    __half2 h = __floats2half2_rn(f0[q], f1[q]);
                    *(__half2*)(smem + SM_XS + (ys*66 + x4*4 + q + 1)*XS_STRIDE + cp*4) = h;
                }
            }
        }
    };
    auto compute = [&](int tap, int buf) {
        const int r = tap / 3, s = tap - r*3;
        const char* Ah = smem + buf*A_BUF;
        const int a_row0 = (mw*32 + qr)*XS_STRIDE + qc*4;
        const int bbase  = ((yl + r)*66 + s + qr)*XS_STRIDE + qc*4;
        #pragma unroll
        for (int ks = 0; ks < 4; ks++) {
            const int kb = ks*32;
            uint32_t ah[2][4];
            #pragma unroll
            for (int mf = 0; mf < 2; mf++) {
                const int ar = a_row0 + mf*(16*XS_STRIDE) + kb;
                ah[mf][0] = *(const uint32_t*)(Ah + ar);
                ah[mf][1] = *(const uint32_t*)(Ah + ar + 8*XS_STRIDE);
                ah[mf][2] = *(const uint32_t*)(Ah + ar + 16);
                ah[mf][3] = *(const uint32_t*)(Ah + ar + 8*XS_STRIDE + 16);
            }
            #pragma unroll
            for (int nf = 0; nf < 8; nf++) {
                const int ba = bbase + nf*(8*XS_STRIDE) + kb;
                const uint32_t b0 = *(const uint32_t*)(smem + SM_XS + ba);
                const uint32_t b1 = *(const uint32_t*)(smem + SM_XS + ba + 16);
                #pragma unroll
                for (int mf = 0; mf < 2; mf++)
                    mma16816h(acc[mf][nf], ah[mf], b0, b1);
            }
        }
    };

    // ---- prologue: zero xs (halo/OOB stay zero), stage ch0 + A(0) ----
    for (int i = tid; i < XS_BYTES/16; i += 512)
        *(uint4*)(smem + SM_XS + i*16) = make_uint4(0u,0u,0u,0u);
    __syncthreads();
    stage_x(0);
    lda(0); sta(0);
    __syncthreads();

    // ---- main loop over (ch, tap) = 18 units, A double-buffered ----
    for (int it = 0; it < 18; it++) {
        const int tap = (it < 9) ? it : it - 9;
        const int buf = it & 1;
        if (it < 17) lda(it + 1);
        compute(tap, buf);
        if (it == 8) {
            __syncthreads();          // all warps done reading xs(ch0)
            stage_x(1);
            sta(buf ^ 1);
            __syncthreads();
        } else if (it < 17) {
            sta(buf ^ 1);
            __syncthreads();
        }
    }

    // ---- epilogue: d-frag -> gmem (float2 stores) ----
    const int y = y0 + yl;
    #pragma unroll
    for (int mf = 0; mf < 2; mf++) {
        const int oc = oc0 + mw*32 + mf*16 + qr;
        float* op0 = out + (((size_t)(b*OC + oc    )*HW) + y)*HW;
        float* op1 = out + (((size_t)(b*OC + oc + 8)*HW) + y)*HW;
        #pragma unroll
        for (int nf = 0; nf < 8; nf++) {
            const int xp = nf*8 + qc*2;
            *(float2*)&op0[xp] = make_float2(acc[mf][nf][0], acc[mf][nf][1]);
            *(float2*)&op1[xp] = make_float2(acc[mf][nf][2], acc[mf][nf][3]);
        }
    }
}

// ---------------------------------------------------------------------------
extern "C" void kernel_launch(void* const* d_in, const int* in_sizes, int n_in,
                              void* d_out, int out_size)
{
    const float* x    = (const float*)d_in[0];  // [16,128,64,64]
    const float* z    = (const float*)d_in[1];  // [16,256]
    const float* bw   = (const float*)d_in[2];  // [256,128,3,3]
    const float* hw   = (const float*)d_in[3];  // [294912,256]
    float*       out  = (float*)d_out;          // [16,256,64,64]

    static bool attr_set = false;
    if (!attr_set) {
        cudaFuncSetAttribute(conv_mma, cudaFuncAttributeMaxDynamicSharedMemorySize, CONV_SMEM);
        attr_set = true;
    }

    gemm_hmma<<<NTOT/(TILES_PER_CTA*64), 256>>>(z, hw);
    build_w<<<BATCH*OC, 128>>>(bw);
    conv_mma<<<dim3(16, 2, BATCH), 512, CONV_SMEM>>>(x, out);
}

// round 13
// speedup vs baseline: 1.0369x; 1.0369x over previous
#include <cuda_runtime.h>
#include <cuda_fp16.h>
#include <cstdint>
#include <math.h>

#define BATCH 16
#define ZD 256
#define OC 256
#define IC 128
#define FANIN (IC*9)          // 1152
#define NTOT (OC*FANIN)       // 294912
#define HW 64

// ---------------- device scratch (no allocation APIs) ----------------
__device__ float g_dw[BATCH*NTOT];             // delta_w [b][n]
__device__ __half g_wh[BATCH*OC*9*IC];         // weights fp16, [b][oc][tap][cin]

// fp16 mma.sync (sm_80-era PTX — valid on plain compute_103 virtual arch)
__device__ __forceinline__ void mma16816h(float* d, const uint32_t* a,
                                          uint32_t b0, uint32_t b1) {
    asm volatile(
        "mma.sync.aligned.m16n8k16.row.col.f32.f16.f16.f32 "
        "{%0,%1,%2,%3}, {%4,%5,%6,%7}, {%8,%9}, {%0,%1,%2,%3};"
        : "+f"(d[0]), "+f"(d[1]), "+f"(d[2]), "+f"(d[3])
        : "r"(a[0]), "r"(a[1]), "r"(a[2]), "r"(a[3]), "r"(b0), "r"(b1));
}

__device__ __forceinline__ uint32_t pack_h2(float a, float b) {
    __half2 h = __floats2half2_rn(a, b);
    return *reinterpret_cast<uint32_t*>(&h);
}

// k-pair permutation within each 32B (k16) group:
// pair p (k = 2p,2p+1; p 0..7) stored at position pos(p) = 2(p&3) | (p>>2).
// Read side: LDS.64 at byte 8*qc returns pairs (qc, qc+4) = m16n8k16 (b0,b1).
__device__ __forceinline__ int kperm_pos(int lp) { return ((lp & 3) << 1) | (lp >> 2); }

// ---------------------------------------------------------------------------
// Kernel A: delta[b][n] = sum_k z[b][k] * head_w[n][k]  via HMMA.
// R8 structure — the measured optimum (57.8us) of five tried variants:
// block-staged LDG.128 (128B/wavefront), single 64n x 256k tile per CTA.
// ---------------------------------------------------------------------------
#define HWS_STRIDE 528     // 256 k * 2B + 16B pad

__global__ void __launch_bounds__(256) gemm_hmma(const float* __restrict__ z,
                                                 const float* __restrict__ hw)
{
    __shared__ uint4 zf[512];            // A-frags: [kk(16)][lane(32)] x 16B
    __shared__ char  hws[64*HWS_STRIDE]; // B fp16, k-pair permuted

    const int tid = threadIdx.x;
    const int n0  = blockIdx.x * 64;

    // ---- build z A-fragments (16 kk x 32 lanes) ----
    #pragma unroll
    for (int u = 0; u < 2; u++) {
        const int s  = tid + u*256;
        const int kk = s >> 5, l = s & 31;
        const int m  = l >> 2;
        const int kb = kk*16 + 2*(l & 3);
        float2 f0 = *(const float2*)&z[m*ZD + kb];
        float2 f1 = *(const float2*)&z[(m+8)*ZD + kb];
        float2 f2 = *(const float2*)&z[m*ZD + kb + 8];
        float2 f3 = *(const float2*)&z[(m+8)*ZD + kb + 8];
        uint4 v;
        v.x = pack_h2(f0.x, f0.y);
        v.y = pack_h2(f1.x, f1.y);
        v.z = pack_h2(f2.x, f2.y);
        v.w = pack_h2(f3.x, f3.y);
        zf[s] = v;
    }

    // ---- stage head_w tile: 64 rows x 256 k, fp32 -> fp16, permuted ----
    #pragma unroll
    for (int half = 0; half < 2; half++) {
        float4 vals[8];
        #pragma unroll
        for (int u = 0; u < 8; u++) {
            const int idx = (half*8 + u)*256 + tid;
            const int row = idx >> 6, kq = idx & 63;
            vals[u] = *(const float4*)&hw[(size_t)(n0 + row)*ZD + kq*4];
        }
        #pragma unroll
        for (int u = 0; u < 8; u++) {
            const int idx = (half*8 + u)*256 + tid;
            const int row = idx >> 6, kq = idx & 63;
            const int g   = kq >> 2;
            const int lp0 = 2*(kq & 3);
            char* rp = hws + row*HWS_STRIDE + g*32;
            *(uint32_t*)(rp + kperm_pos(lp0)*4)     = pack_h2(vals[u].x, vals[u].y);
            *(uint32_t*)(rp + kperm_pos(lp0 + 1)*4) = pack_h2(vals[u].z, vals[u].w);
        }
    }
    __syncthreads();

    // ---- compute: warp w -> n rows w*8..w*8+7, K=256 ----
    const int wid = tid >> 5, lane = tid & 31;
    const int qr = lane >> 2, qc = lane & 3;

    float d[4] = {0.f, 0.f, 0.f, 0.f};
    const char* bp = hws + (wid*8 + qr)*HWS_STRIDE + qc*8;
    #pragma unroll
    for (int kk = 0; kk < 16; kk++) {
        uint4 a = zf[kk*32 + lane];
        uint2 b = *(const uint2*)(bp + kk*32);
        mma16816h(d, (const uint32_t*)&a, b.x, b.y);
    }

    const int n = n0 + wid*8 + 2*qc;
    *(float2*)&g_dw[(size_t)qr*NTOT + n]       = make_float2(d[0], d[1]);
    *(float2*)&g_dw[(size_t)(qr + 8)*NTOT + n] = make_float2(d[2], d[3]);
}

// ---------------------------------------------------------------------------
// Kernel B: standardize + build weights, emit fp16, [b][oc][tap][cin].
// Transpose via smem so global writes are coalesced 8B stores.
// ---------------------------------------------------------------------------
__global__ void __launch_bounds__(128) build_w(const float* __restrict__ base)
{
    __shared__ __half ws[FANIN];        // [tap][cin]

    const int b  = blockIdx.x >> 8;
    const int oc = blockIdx.x & 255;
    const int tid = threadIdx.x;

    const float* dwp = &g_dw[(size_t)b*NTOT + oc*FANIN];

    float v[9];
    float s = 0.f, sq = 0.f;
    #pragma unroll
    for (int t = 0; t < 9; t++) {
        v[t] = dwp[tid + t*128];
        s  += v[t];
        sq += v[t]*v[t];
    }
    #pragma unroll
    for (int off = 16; off; off >>= 1) {
        s  += __shfl_xor_sync(0xffffffffu, s,  off);
        sq += __shfl_xor_sync(0xffffffffu, sq, off);
    }
    __shared__ float ss[4], ssq[4];
    const int wid = tid >> 5;
    if ((tid & 31) == 0) { ss[wid] = s; ssq[wid] = sq; }
    __syncthreads();
    s  = ss[0] + ss[1] + ss[2] + ss[3];
    sq = ssq[0] + ssq[1] + ssq[2] + ssq[3];

    const float inv_n = 1.0f / (float)FANIN;
    float mu  = s * inv_n;
    float var = sq * inv_n - mu*mu;
    float rs  = rsqrtf(var + 1e-5f);
    const float inv_sqrt2 = 0.70710678118654752440f;
    float c1 = rs * sqrtf(2.0f / (float)FANIN) * inv_sqrt2;

    const float* bw = &base[(size_t)oc*FANIN];
    #pragma unroll
    for (int t = 0; t < 9; t++) {
        int i = tid + t*128;           // i = cin*9 + tap
        int cin = i / 9, tap = i - cin*9;
        float w = bw[i]*inv_sqrt2 + (v[t] - mu)*c1;
        ws[tap*IC + cin] = __float2half(w);
    }
    __syncthreads();

    // coalesced flush: 1152 halves = 288 x 8B
    uint2* dst = (uint2*)&g_wh[(size_t)(b*OC + oc)*9*IC];
    const uint2* src = (const uint2*)ws;
    #pragma unroll
    for (int i = tid; i < 288; i += 128) dst[i] = src[i];
}

// ---------------------------------------------------------------------------
// Kernel C: implicit-GEMM conv via mma.sync fp16 single-pass, fp32 accum.
// CTA = (4 y-rows, 128-oc tile, b). 512 threads = 16 warps, warp tile 32oc x 64n.
// At the 512 MAC/cyc/SM HMMA ceiling — do not touch.
// ---------------------------------------------------------------------------
#define XS_STRIDE 144                  // bytes per (y,x) row of 64 cin fp16 (+16B pad)
#define XS_BYTES  (6*66*XS_STRIDE)     // 57024
#define A_BUF     18432                // one A buffer: 128 oc x 144B
#define SM_XS     36864                // after 2 A buffers
#define CONV_SMEM (SM_XS + XS_BYTES)   // 93888

__global__ void __launch_bounds__(512, 1) conv_mma(const float* __restrict__ x,
                                                   float* __restrict__ out)
{
    extern __shared__ char smem[];
    const int tid  = threadIdx.x;
    const int wid  = tid >> 5;
    const int lane = tid & 31;
    const int y0   = blockIdx.x * 4;
    const int oc0  = blockIdx.y * 128;
    const int b    = blockIdx.z;

    const int mw = wid & 3;       // oc quarter (32)
    const int yl = wid >> 2;      // local y row
    const int qr = lane >> 2;     // 0..7
    const int qc = lane & 3;      // 0..3

    float acc[2][8][4];
    #pragma unroll
    for (int mf = 0; mf < 2; mf++)
        #pragma unroll
        for (int nf = 0; nf < 8; nf++)
            #pragma unroll
            for (int q = 0; q < 4; q++) acc[mf][nf][q] = 0.f;

    uint4 nv[2];   // in-flight A tile, 2 chunks per thread

    // ---- helpers ----
    auto lda = [&](int it) {
        const int ch = it / 9, tap = it - ch*9;
        const size_t abase = ((size_t)((b*OC + oc0)*9 + tap))*IC + (size_t)ch*64;
        #pragma unroll
        for (int u = 0; u < 2; u++) {
            const int i = tid + u*512;
            const int row = i >> 3, j = i & 7;
            const size_t off8 = (abase + (size_t)row*(9*IC)) / 8 + j;   // uint4 idx
            nv[u] = ((const uint4*)g_wh)[off8];
        }
    };
    auto sta = [&](int buf) {
        char* base = smem + buf*A_BUF;
        #pragma unroll
        for (int u = 0; u < 2; u++) {
            const int i = tid + u*512;
            const int row = i >> 3, j = i & 7;
            *(uint4*)(base + row*XS_STRIDE + j*16) = nv[u];
        }
    };
    auto stage_x = [&](int ch) {
        for (int i = tid; i < 6*32*16; i += 512) {
            const int ys  = i >> 9;
            const int rem = i & 511;
            const int cp  = rem >> 4;      // c-pair 0..31
            const int x4  = rem & 15;
            const int gy  = y0 - 1 + ys;
            if (gy >= 0 && gy < HW) {
                const float4 v0 = *(const float4*)
                    &x[(((size_t)(b*IC + ch*64 + cp*2    ))*HW + gy)*HW + x4*4];
                const float4 v1 = *(const float4*)
                    &x[(((size_t)(b*IC + ch*64 + cp*2 + 1))*HW + gy)*HW + x4*4];
                const float f0[4] = {v0.x, v0.y, v0.z, v0.w};
                const float f1[4] = {v1.x, v1.y, v1.z, v1.w};
                #pragma unroll
                for (int q = 0; q < 4; q++) {
                    __half2 h = __floats2half2_rn(f0[q], f1[q]);
                    *(__half2*)(smem + SM_XS + (ys*66 + x4*4 + q + 1)*XS_STRIDE + cp*4) = h;
                }
            }
        }
    };
    auto compute = [&](int tap, int buf) {
        const int r = tap / 3, s = tap - r*3;
        const char* Ah = smem + buf*A_BUF;
        const int a_row0 = (mw*32 + qr)*XS_STRIDE + qc*4;
        const int bbase  = ((yl + r)*66 + s + qr)*XS_STRIDE + qc*4;
        #pragma unroll
        for (int ks = 0; ks < 4; ks++) {
            const int kb = ks*32;
            uint32_t ah[2][4];
            #pragma unroll
            for (int mf = 0; mf < 2; mf++) {
                const int ar = a_row0 + mf*(16*XS_STRIDE) + kb;
                ah[mf][0] = *(const uint32_t*)(Ah + ar);
                ah[mf][1] = *(const uint32_t*)(Ah + ar + 8*XS_STRIDE);
                ah[mf][2] = *(const uint32_t*)(Ah + ar + 16);
                ah[mf][3] = *(const uint32_t*)(Ah + ar + 8*XS_STRIDE + 16);
            }
            #pragma unroll
            for (int nf = 0; nf < 8; nf++) {
                const int ba = bbase + nf*(8*XS_STRIDE) + kb;
                const uint32_t b0 = *(const uint32_t*)(smem + SM_XS + ba);
                const uint32_t b1 = *(const uint32_t*)(smem + SM_XS + ba + 16);
                #pragma unroll
                for (int mf = 0; mf < 2; mf++)
                    mma16816h(acc[mf][nf], ah[mf], b0, b1);
            }
        }
    };

    // ---- prologue: zero xs (halo/OOB stay zero), stage ch0 + A(0) ----
    for (int i = tid; i < XS_BYTES/16; i += 512)
        *(uint4*)(smem + SM_XS + i*16) = make_uint4(0u,0u,0u,0u);
    __syncthreads();
    stage_x(0);
    lda(0); sta(0);
    __syncthreads();

    // ---- main loop over (ch, tap) = 18 units, A double-buffered ----
    for (int it = 0; it < 18; it++) {
        const int tap = (it < 9) ? it : it - 9;
        const int buf = it & 1;
        if (it < 17) lda(it + 1);
        compute(tap, buf);
        if (it == 8) {
            __syncthreads();          // all warps done reading xs(ch0)
            stage_x(1);
            sta(buf ^ 1);
            __syncthreads();
        } else if (it < 17) {
            sta(buf ^ 1);
            __syncthreads();
        }
    }

    // ---- epilogue: d-frag -> gmem (float2 stores) ----
    const int y = y0 + yl;
    #pragma unroll
    for (int mf = 0; mf < 2; mf++) {
        const int oc = oc0 + mw*32 + mf*16 + qr;
        float* op0 = out + (((size_t)(b*OC + oc    )*HW) + y)*HW;
        float* op1 = out + (((size_t)(b*OC + oc + 8)*HW) + y)*HW;
        #pragma unroll
        for (int nf = 0; nf < 8; nf++) {
            const int xp = nf*8 + qc*2;
            *(float2*)&op0[xp] = make_float2(acc[mf][nf][0], acc[mf][nf][1]);
            *(float2*)&op1[xp] = make_float2(acc[mf][nf][2], acc[mf][nf][3]);
        }
    }
}

// ---------------------------------------------------------------------------
extern "C" void kernel_launch(void* const* d_in, const int* in_sizes, int n_in,
                              void* d_out, int out_size)
{
    const float* x    = (const float*)d_in[0];  // [16,128,64,64]
    const float* z    = (const float*)d_in[1];  // [16,256]
    const float* bw   = (const float*)d_in[2];  // [256,128,3,3]
    const float* hw   = (const float*)d_in[3];  // [294912,256]
    float*       out  = (float*)d_out;          // [16,256,64,64]

    static bool attr_set = false;
    if (!attr_set) {
        cudaFuncSetAttribute(conv_mma, cudaFuncAttributeMaxDynamicSharedMemorySize, CONV_SMEM);
        attr_set = true;
    }

    gemm_hmma<<<NTOT/64, 256>>>(z, hw);
    build_w<<<BATCH*OC, 128>>>(bw);
    conv_mma<<<dim3(16, 2, BATCH), 512, CONV_SMEM>>>(x, out);
}

// round 14
// speedup vs baseline: 1.0386x; 1.0016x over previous
#include <cuda_runtime.h>
#include <cuda_fp16.h>
#include <cstdint>
#include <math.h>

#define BATCH 16
#define ZD 256
#define OC 256
#define IC 128
#define FANIN (IC*9)          // 1152
#define NTOT (OC*FANIN)       // 294912
#define HW 64

// ---------------- device scratch (no allocation APIs) ----------------
__device__ float g_dw[BATCH*NTOT];             // delta_w [b][n]
__device__ __half g_wh[BATCH*OC*9*IC];         // weights fp16, [b][oc][tap][cin]

// fp16 mma.sync (sm_80-era PTX — valid on plain compute_103 virtual arch)
__device__ __forceinline__ void mma16816h(float* d, const uint32_t* a,
                                          uint32_t b0, uint32_t b1) {
    asm volatile(
        "mma.sync.aligned.m16n8k16.row.col.f32.f16.f16.f32 "
        "{%0,%1,%2,%3}, {%4,%5,%6,%7}, {%8,%9}, {%0,%1,%2,%3};"
        : "+f"(d[0]), "+f"(d[1]), "+f"(d[2]), "+f"(d[3])
        : "r"(a[0]), "r"(a[1]), "r"(a[2]), "r"(a[3]), "r"(b0), "r"(b1));
}

__device__ __forceinline__ uint32_t pack_h2(float a, float b) {
    __half2 h = __floats2half2_rn(a, b);
    return *reinterpret_cast<uint32_t*>(&h);
}

// k-pair permutation within each 32B (k16) group:
// pair p stored at pos(p) = 2(p&3) | (p>>2); LDS.64 at 8*qc -> (b0,b1).
__device__ __forceinline__ int kperm_pos(int lp) { return ((lp & 3) << 1) | (lp >> 2); }

// ---------------------------------------------------------------------------
// Kernel A: delta[b][n] = sum_k z[b][k] * head_w[n][k]  via HMMA.
// R8 structure (measured optimum). tile_off selects the n-tile range.
// ---------------------------------------------------------------------------
#define HWS_STRIDE 528     // 256 k * 2B + 16B pad

__global__ void __launch_bounds__(256) gemm_hmma(const float* __restrict__ z,
                                                 const float* __restrict__ hw,
                                                 int tile_off)
{
    __shared__ uint4 zf[512];            // A-frags: [kk(16)][lane(32)] x 16B
    __shared__ char  hws[64*HWS_STRIDE]; // B fp16, k-pair permuted

    const int tid = threadIdx.x;
    const int n0  = (blockIdx.x + tile_off) * 64;

    // ---- build z A-fragments (16 kk x 32 lanes) ----
    #pragma unroll
    for (int u = 0; u < 2; u++) {
        const int s  = tid + u*256;
        const int kk = s >> 5, l = s & 31;
        const int m  = l >> 2;
        const int kb = kk*16 + 2*(l & 3);
        float2 f0 = *(const float2*)&z[m*ZD + kb];
        float2 f1 = *(const float2*)&z[(m+8)*ZD + kb];
        float2 f2 = *(const float2*)&z[m*ZD + kb + 8];
        float2 f3 = *(const float2*)&z[(m+8)*ZD + kb + 8];
        uint4 v;
        v.x = pack_h2(f0.x, f0.y);
        v.y = pack_h2(f1.x, f1.y);
        v.z = pack_h2(f2.x, f2.y);
        v.w = pack_h2(f3.x, f3.y);
        zf[s] = v;
    }

    // ---- stage head_w tile: 64 rows x 256 k, fp32 -> fp16, permuted ----
    #pragma unroll
    for (int half = 0; half < 2; half++) {
        float4 vals[8];
        #pragma unroll
        for (int u = 0; u < 8; u++) {
            const int idx = (half*8 + u)*256 + tid;
            const int row = idx >> 6, kq = idx & 63;
            vals[u] = *(const float4*)&hw[(size_t)(n0 + row)*ZD + kq*4];
        }
        #pragma unroll
        for (int u = 0; u < 8; u++) {
            const int idx = (half*8 + u)*256 + tid;
            const int row = idx >> 6, kq = idx & 63;
            const int g   = kq >> 2;
            const int lp0 = 2*(kq & 3);
            char* rp = hws + row*HWS_STRIDE + g*32;
            *(uint32_t*)(rp + kperm_pos(lp0)*4)     = pack_h2(vals[u].x, vals[u].y);
            *(uint32_t*)(rp + kperm_pos(lp0 + 1)*4) = pack_h2(vals[u].z, vals[u].w);
        }
    }
    __syncthreads();

    // ---- compute: warp w -> n rows w*8..w*8+7, K=256 ----
    const int wid = tid >> 5, lane = tid & 31;
    const int qr = lane >> 2, qc = lane & 3;

    float d[4] = {0.f, 0.f, 0.f, 0.f};
    const char* bp = hws + (wid*8 + qr)*HWS_STRIDE + qc*8;
    #pragma unroll
    for (int kk = 0; kk < 16; kk++) {
        uint4 a = zf[kk*32 + lane];
        uint2 b = *(const uint2*)(bp + kk*32);
        mma16816h(d, (const uint32_t*)&a, b.x, b.y);
    }

    const int n = n0 + wid*8 + 2*qc;
    *(float2*)&g_dw[(size_t)qr*NTOT + n]       = make_float2(d[0], d[1]);
    *(float2*)&g_dw[(size_t)(qr + 8)*NTOT + n] = make_float2(d[2], d[3]);
}

// ---------------------------------------------------------------------------
// Kernel B: standardize + build weights, emit fp16, [b][oc][tap][cin].
// Grid = BATCH * n_oc; oc = (blockIdx.x & (n_oc-1)) + oc_off (n_oc = 128 here).
// ---------------------------------------------------------------------------
__global__ void __launch_bounds__(128) build_w(const float* __restrict__ base,
                                               int oc_off)
{
    __shared__ __half ws[FANIN];        // [tap][cin]

    const int b  = blockIdx.x >> 7;
    const int oc = (blockIdx.x & 127) + oc_off;
    const int tid = threadIdx.x;

    const float* dwp = &g_dw[(size_t)b*NTOT + oc*FANIN];

    float v[9];
    float s = 0.f, sq = 0.f;
    #pragma unroll
    for (int t = 0; t < 9; t++) {
        v[t] = dwp[tid + t*128];
        s  += v[t];
        sq += v[t]*v[t];
    }
    #pragma unroll
    for (int off = 16; off; off >>= 1) {
        s  += __shfl_xor_sync(0xffffffffu, s,  off);
        sq += __shfl_xor_sync(0xffffffffu, sq, off);
    }
    __shared__ float ss[4], ssq[4];
    const int wid = tid >> 5;
    if ((tid & 31) == 0) { ss[wid] = s; ssq[wid] = sq; }
    __syncthreads();
    s  = ss[0] + ss[1] + ss[2] + ss[3];
    sq = ssq[0] + ssq[1] + ssq[2] + ssq[3];

    const float inv_n = 1.0f / (float)FANIN;
    float mu  = s * inv_n;
    float var = sq * inv_n - mu*mu;
    float rs  = rsqrtf(var + 1e-5f);
    const float inv_sqrt2 = 0.70710678118654752440f;
    float c1 = rs * sqrtf(2.0f / (float)FANIN) * inv_sqrt2;

    const float* bw = &base[(size_t)oc*FANIN];
    #pragma unroll
    for (int t = 0; t < 9; t++) {
        int i = tid + t*128;           // i = cin*9 + tap
        int cin = i / 9, tap = i - cin*9;
        float w = bw[i]*inv_sqrt2 + (v[t] - mu)*c1;
        ws[tap*IC + cin] = __float2half(w);
    }
    __syncthreads();

    uint2* dst = (uint2*)&g_wh[(size_t)(b*OC + oc)*9*IC];
    const uint2* src = (const uint2*)ws;
    #pragma unroll
    for (int i = tid; i < 288; i += 128) dst[i] = src[i];
}

// ---------------------------------------------------------------------------
// Kernel C: implicit-GEMM conv via mma.sync fp16 single-pass, fp32 accum.
// CTA = (4 y-rows, 128-oc tile @ oc_off + blockIdx.y*128, b).
// At the 512 MAC/cyc/SM HMMA ceiling — numerics untouched.
// ---------------------------------------------------------------------------
#define XS_STRIDE 144
#define XS_BYTES  (6*66*XS_STRIDE)     // 57024
#define A_BUF     18432
#define SM_XS     36864
#define CONV_SMEM (SM_XS + XS_BYTES)   // 93888

__global__ void __launch_bounds__(512, 1) conv_mma(const float* __restrict__ x,
                                                   float* __restrict__ out,
                                                   int oc_off)
{
    extern __shared__ char smem[];
    const int tid  = threadIdx.x;
    const int wid  = tid >> 5;
    const int lane = tid & 31;
    const int y0   = blockIdx.x * 4;
    const int oc0  = blockIdx.y * 128 + oc_off;
    const int b    = blockIdx.z;

    const int mw = wid & 3;
    const int yl = wid >> 2;
    const int qr = lane >> 2;
    const int qc = lane & 3;

    float acc[2][8][4];
    #pragma unroll
    for (int mf = 0; mf < 2; mf++)
        #pragma unroll
        for (int nf = 0; nf < 8; nf++)
            #pragma unroll
            for (int q = 0; q < 4; q++) acc[mf][nf][q] = 0.f;

    uint4 nv[2];

    auto lda = [&](int it) {
        const int ch = it / 9, tap = it - ch*9;
        const size_t abase = ((size_t)((b*OC + oc0)*9 + tap))*IC + (size_t)ch*64;
        #pragma unroll
        for (int u = 0; u < 2; u++) {
            const int i = tid + u*512;
            const int row = i >> 3, j = i & 7;
            const size_t off8 = (abase + (size_t)row*(9*IC)) / 8 + j;
            nv[u] = ((const uint4*)g_wh)[off8];
        }
    };
    auto sta = [&](int buf) {
        char* base = smem + buf*A_BUF;
        #pragma unroll
        for (int u = 0; u < 2; u++) {
            const int i = tid + u*512;
            const int row = i >> 3, j = i & 7;
            *(uint4*)(base + row*XS_STRIDE + j*16) = nv[u];
        }
    };
    auto stage_x = [&](int ch) {
        for (int i = tid; i < 6*32*16; i += 512) {
            const int ys  = i >> 9;
            const int rem = i & 511;
            const int cp  = rem >> 4;
            const int x4  = rem & 15;
            const int gy  = y0 - 1 + ys;
            if (gy >= 0 && gy < HW) {
                const float4 v0 = *(const float4*)
                    &x[(((size_t)(b*IC + ch*64 + cp*2    ))*HW + gy)*HW + x4*4];
                const float4 v1 = *(const float4*)
                    &x[(((size_t)(b*IC + ch*64 + cp*2 + 1))*HW + gy)*HW + x4*4];
                const float f0[4] = {v0.x, v0.y, v0.z, v0.w};
                const float f1[4] = {v1.x, v1.y, v1.z, v1.w};
                #pragma unroll
                for (int q = 0; q < 4; q++) {
                    __half2 h = __floats2half2_rn(f0[q], f1[q]);
                    *(__half2*)(smem + SM_XS + (ys*66 + x4*4 + q + 1)*XS_STRIDE + cp*4) = h;
                }
            }
        }
    };
    auto compute = [&](int tap, int buf) {
        const int r = tap / 3, s = tap - r*3;
        const char* Ah = smem + buf*A_BUF;
        const int a_row0 = (mw*32 + qr)*XS_STRIDE + qc*4;
        const int bbase  = ((yl + r)*66 + s + qr)*XS_STRIDE + qc*4;
        #pragma unroll
        for (int ks = 0; ks < 4; ks++) {
            const int kb = ks*32;
            uint32_t ah[2][4];
            #pragma unroll
            for (int mf = 0; mf < 2; mf++) {
                const int ar = a_row0 + mf*(16*XS_STRIDE) + kb;
                ah[mf][0] = *(const uint32_t*)(Ah + ar);
                ah[mf][1] = *(const uint32_t*)(Ah + ar + 8*XS_STRIDE);
                ah[mf][2] = *(const uint32_t*)(Ah + ar + 16);
                ah[mf][3] = *(const uint32_t*)(Ah + ar + 8*XS_STRIDE + 16);
            }
            #pragma unroll
            for (int nf = 0; nf < 8; nf++) {
                const int ba = bbase + nf*(8*XS_STRIDE) + kb;
                const uint32_t b0 = *(const uint32_t*)(smem + SM_XS + ba);
                const uint32_t b1 = *(const uint32_t*)(smem + SM_XS + ba + 16);
                #pragma unroll
                for (int mf = 0; mf < 2; mf++)
                    mma16816h(acc[mf][nf], ah[mf], b0, b1);
            }
        }
    };

    for (int i = tid; i < XS_BYTES/16; i += 512)
        *(uint4*)(smem + SM_XS + i*16) = make_uint4(0u,0u,0u,0u);
    __syncthreads();
    stage_x(0);
    lda(0); sta(0);
    __syncthreads();

    for (int it = 0; it < 18; it++) {
        const int tap = (it < 9) ? it : it - 9;
        const int buf = it & 1;
        if (it < 17) lda(it + 1);
        compute(tap, buf);
        if (it == 8) {
            __syncthreads();
            stage_x(1);
            sta(buf ^ 1);
            __syncthreads();
        } else if (it < 17) {
            sta(buf ^ 1);
            __syncthreads();
        }
    }

    const int y = y0 + yl;
    #pragma unroll
    for (int mf = 0; mf < 2; mf++) {
        const int oc = oc0 + mw*32 + mf*16 + qr;
        float* op0 = out + (((size_t)(b*OC + oc    )*HW) + y)*HW;
        float* op1 = out + (((size_t)(b*OC + oc + 8)*HW) + y)*HW;
        #pragma unroll
        for (int nf = 0; nf < 8; nf++) {
            const int xp = nf*8 + qc*2;
            *(float2*)&op0[xp] = make_float2(acc[mf][nf][0], acc[mf][nf][1]);
            *(float2*)&op1[xp] = make_float2(acc[mf][nf][2], acc[mf][nf][3]);
        }
    }
}

// ---------------------------------------------------------------------------
// Launcher: oc-half pipelined across 2 streams so gemm(h1) (DRAM-bound)
// overlaps conv(h0) (tensor-bound). Falls back to the sequential R13 path
// if stream/event creation fails.
// ---------------------------------------------------------------------------
extern "C" void kernel_launch(void* const* d_in, const int* in_sizes, int n_in,
                              void* d_out, int out_size)
{
    const float* x    = (const float*)d_in[0];  // [16,128,64,64]
    const float* z    = (const float*)d_in[1];  // [16,256]
    const float* bw   = (const float*)d_in[2];  // [256,128,3,3]
    const float* hw   = (const float*)d_in[3];  // [294912,256]
    float*       out  = (float*)d_out;          // [16,256,64,64]

    static bool init_done = false;
    static bool two_streams = false;
    static cudaStream_t s2 = 0;
    static cudaEvent_t evA = 0, evB = 0;
    if (!init_done) {
        cudaFuncSetAttribute(conv_mma, cudaFuncAttributeMaxDynamicSharedMemorySize, CONV_SMEM);
        two_streams =
            (cudaStreamCreateWithFlags(&s2, cudaStreamNonBlocking) == cudaSuccess) &&
            (cudaEventCreateWithFlags(&evA, cudaEventDisableTiming) == cudaSuccess) &&
            (cudaEventCreateWithFlags(&evB, cudaEventDisableTiming) == cudaSuccess);
        init_done = true;
    }

    if (two_streams) {
        // half 0 (oc < 128): gemm tiles 0..2303
        gemm_hmma<<<2304, 256>>>(z, hw, 0);
        build_w<<<BATCH*128, 128>>>(bw, 0);
        cudaEventRecord(evA, 0);
        cudaStreamWaitEvent(s2, evA, 0);
        conv_mma<<<dim3(16, 1, BATCH), 512, CONV_SMEM, s2>>>(x, out, 0);
        // half 1 (oc >= 128) proceeds on stream 0 concurrently with conv(h0)
        gemm_hmma<<<2304, 256>>>(z, hw, 2304);
        build_w<<<BATCH*128, 128>>>(bw, 128);
        conv_mma<<<dim3(16, 1, BATCH), 512, CONV_SMEM>>>(x, out, 128);
        // join: stream 0 completion implies conv(h0) done
        cudaEventRecord(evB, s2);
        cudaStreamWaitEvent(0, evB, 0);
    } else {
        // sequential fallback == R13
        gemm_hmma<<<NTOT/64, 256>>>(z, hw, 0);
        build_w<<<BATCH*128, 128>>>(bw, 0);
        build_w<<<BATCH*128, 128>>>(bw, 128);
        conv_mma<<<dim3(16, 2, BATCH), 512, CONV_SMEM>>>(x, out, 0);
    }
}